// round 1
// baseline (speedup 1.0000x reference)
#include <cuda_runtime.h>

// Conv2d: N=32, C_in=64, H=W=64, C_out=128, 3x3, stride 1, pad 1, fp32.
// input  : (32, 64, 64, 64)  NCHW
// weight : (64*3*3, 128)     patch axis = ci*9 + ky*3 + kx
// bias   : (1, 128, 1, 1)
// output : (32, 128, 64, 64) NCHW
//
// Block tile: one n, 4 output rows, all 64 x, 32 c_out.
// 256 threads: x = tid&63, tg = tid>>6 (c_out subgroup of 8 channels).
// Each thread: 4 rows x 8 channels = 32 outputs, held as 4x4 packed f32x2.
// Per-ci staging: input 6x66 halo tile + 9x32 weight slab in smem.
// Inner math uses Blackwell packed fma.rn.f32x2 (2 MACs/inst).

#define CI   64
#define HW_  64
#define CO   128

__global__ __launch_bounds__(256, 4)
void conv3x3_kernel(const float* __restrict__ in,
                    const float* __restrict__ w,
                    const float* __restrict__ bias,
                    float* __restrict__ out)
{
    __shared__ __align__(16) float sIn[6][68];   // rows y0-1..y0+4, cols -1..64 (stride 68)
    __shared__ __align__(16) float sW[9][32];    // [ky*3+kx][co_local]

    const int tid = threadIdx.x;
    const int x   = tid & 63;
    const int tg  = tid >> 6;          // 0..3 -> c_out subgroup (8 channels)
    const int y0      = blockIdx.x * 4;
    const int co_base = blockIdx.y * 32;
    const int n       = blockIdx.z;

    unsigned long long acc[4][4];
#pragma unroll
    for (int r = 0; r < 4; ++r)
#pragma unroll
        for (int p = 0; p < 4; ++p) acc[r][p] = 0ull;

    const float* in_n = in + (size_t)n * CI * HW_ * HW_;

    for (int ci = 0; ci < CI; ++ci) {
        __syncthreads();  // previous iteration's compute done before overwrite

        // ---- stage input halo tile: 6 rows x 66 cols (zero-padded) ----
        const float* in_c = in_n + (size_t)ci * HW_ * HW_;
#pragma unroll
        for (int e = tid; e < 6 * 66; e += 256) {
            int row = e / 66;
            int col = e - row * 66;
            int gy = y0 - 1 + row;
            int gx = col - 1;
            float v = 0.0f;
            if ((unsigned)gy < (unsigned)HW_ && (unsigned)gx < (unsigned)HW_)
                v = in_c[gy * HW_ + gx];
            sIn[row][col] = v;
        }

        // ---- stage weights: 9 taps x 32 c_out ----
        const float* wp = w + (size_t)(ci * 9) * CO + co_base;
#pragma unroll
        for (int e = tid; e < 288; e += 256) {
            int kk = e >> 5;
            int c  = e & 31;
            sW[kk][c] = wp[kk * CO + c];
        }
        __syncthreads();

        // ---- compute: 9 taps x 4 rows x 8 channels (packed as 4 f32x2) ----
#pragma unroll
        for (int ky = 0; ky < 3; ++ky) {
#pragma unroll
            for (int kx = 0; kx < 3; ++kx) {
                const unsigned long long* wv =
                    (const unsigned long long*)&sW[ky * 3 + kx][tg * 8];
                unsigned long long w0 = wv[0];
                unsigned long long w1 = wv[1];
                unsigned long long w2 = wv[2];
                unsigned long long w3 = wv[3];
#pragma unroll
                for (int r = 0; r < 4; ++r) {
                    float a = sIn[ky + r][x + kx];
                    unsigned long long ap;
                    asm("mov.b64 %0, {%1, %1};"
                        : "=l"(ap) : "r"(__float_as_uint(a)));
                    asm("fma.rn.f32x2 %0, %1, %2, %0;"
                        : "+l"(acc[r][0]) : "l"(ap), "l"(w0));
                    asm("fma.rn.f32x2 %0, %1, %2, %0;"
                        : "+l"(acc[r][1]) : "l"(ap), "l"(w1));
                    asm("fma.rn.f32x2 %0, %1, %2, %0;"
                        : "+l"(acc[r][2]) : "l"(ap), "l"(w2));
                    asm("fma.rn.f32x2 %0, %1, %2, %0;"
                        : "+l"(acc[r][3]) : "l"(ap), "l"(w3));
                }
            }
        }
    }

    // ---- epilogue: unpack, add bias, store (coalesced in x) ----
#pragma unroll
    for (int r = 0; r < 4; ++r) {
        int y = y0 + r;
#pragma unroll
        for (int p = 0; p < 4; ++p) {
            unsigned lo, hi;
            asm("mov.b64 {%0, %1}, %2;" : "=r"(lo), "=r"(hi) : "l"(acc[r][p]));
            int co = co_base + tg * 8 + 2 * p;
            float v0 = __uint_as_float(lo) + bias[co];
            float v1 = __uint_as_float(hi) + bias[co + 1];
            size_t o0 = (((size_t)n * CO + co) * HW_ + y) * HW_ + x;
            out[o0] = v0;
            out[o0 + (size_t)HW_ * HW_] = v1;
        }
    }
}

extern "C" void kernel_launch(void* const* d_in, const int* in_sizes, int n_in,
                              void* d_out, int out_size)
{
    const float* in   = (const float*)d_in[0];
    const float* w    = (const float*)d_in[1];
    const float* bias = (const float*)d_in[2];
    float* out        = (float*)d_out;

    dim3 grid(16 /* y tiles */, 4 /* co groups */, 32 /* n */);
    conv3x3_kernel<<<grid, 256>>>(in, w, bias, out);
}

// round 3
// speedup vs baseline: 2.2739x; 2.2739x over previous
#include <cuda_runtime.h>
#include <cstdint>

// Conv2d N=32, Cin=64, 64x64, Cout=128, 3x3 s1 p1, fp32.
// Implicit GEMM on mma.sync.m16n8k8.tf32 (baseline ISA; tcgen05 PTX features
// are unavailable because the harness compiles at compute_103, not _103a).
//
// CTA: one n, 4 output rows -> GEMM tile M=256 (4y x 64x), N=128 (all co),
// K=576 = 2 ci-chunks x 9 taps x 32. 8 warps, warp tile 64x64.
// SMEM per chunk: A halo (32ci x 6y x 66x, tf32) + B all 9 taps pre-paired
// for LDS.64 b-fragment loads. 203KB -> 1 CTA/SM.

#define HW  64
#define CO  128
#define CIN 64

#define SB_ROW    264                 // 128 co pairs (256 floats) + 8 pad
#define SB_FLOATS (144 * SB_ROW)      // 9 taps * 4 ksteps * 4 j rows
#define SA_OFF    SB_FLOATS
#define SA_CI     396                 // 6 rows * 66 cols
#define SMEM_FLOATS (SB_FLOATS + 32 * SA_CI)
#define SMEM_BYTES  (SMEM_FLOATS * 4) // 202,752 B

__device__ __forceinline__ uint32_t f2tf32(float f) {
    uint32_t r; asm("cvt.rna.tf32.f32 %0, %1;" : "=r"(r) : "f"(f)); return r;
}
__device__ __forceinline__ void mma8(float c[4], const uint32_t a[4], uint2 b) {
    asm volatile(
        "mma.sync.aligned.m16n8k8.row.col.f32.tf32.tf32.f32 "
        "{%0,%1,%2,%3}, {%4,%5,%6,%7}, {%8,%9}, {%0,%1,%2,%3};"
        : "+f"(c[0]), "+f"(c[1]), "+f"(c[2]), "+f"(c[3])
        : "r"(a[0]), "r"(a[1]), "r"(a[2]), "r"(a[3]), "r"(b.x), "r"(b.y));
}

__global__ void __launch_bounds__(256, 1)
conv_mma_kernel(const float* __restrict__ in, const float* __restrict__ w,
                const float* __restrict__ bias, float* __restrict__ out)
{
    extern __shared__ float sm[];

    const int tid   = threadIdx.x;
    const int lane  = tid & 31;
    const int warp  = tid >> 5;
    const int warpM = warp >> 1;      // 0..3 -> y row within tile
    const int warpN = warp & 1;       // 0..1 -> co 64-block
    const int y0    = blockIdx.x * 4;
    const int n     = blockIdx.y;

    const int r  = lane >> 2;         // 0..7
    const int j  = lane & 3;          // 0..3

    float acc[4][8][4];
#pragma unroll
    for (int mt = 0; mt < 4; ++mt)
#pragma unroll
        for (int nt = 0; nt < 8; ++nt)
#pragma unroll
            for (int q = 0; q < 4; ++q) acc[mt][nt][q] = 0.f;

    for (int chunk = 0; chunk < 2; ++chunk) {
        const int cib = chunk * 32;
        __syncthreads();   // previous chunk's LDS reads complete

        // ---- stage A: 32 ci x 6 halo rows x 66 cols, tf32-rounded ----
        const float* inb = in + ((size_t)n * CIN + cib) * (HW * HW);
        for (int e = tid; e < 32 * SA_CI; e += 256) {
            int p   = e / 66;         // ci*6 + row
            int col = e - p * 66;
            int ci  = p / 6;
            int row = p - ci * 6;
            int gy  = y0 - 1 + row;
            int gx  = col - 1;
            float v = 0.f;
            if ((unsigned)gy < (unsigned)HW && (unsigned)gx < (unsigned)HW)
                v = inb[((size_t)ci * HW + gy) * HW + gx];
            sm[SA_OFF + ci * SA_CI + row * 66 + col] = __uint_as_float(f2tf32(v));
        }

        // ---- stage B: rows (tap, s, j) hold pairs (k, k+4) per co ----
        const float* wb = w + (size_t)cib * 9 * CO;
        for (int e = tid; e < 144 * 128; e += 256) {
            int co   = e & 127;
            int rowp = e >> 7;            // 0..143
            int tap  = rowp >> 4;
            int s    = (rowp >> 2) & 3;
            int jj   = rowp & 3;
            int k    = s * 8 + jj;
            float v0 = wb[((size_t)k * 9 + tap) * CO + co];
            float v1 = wb[((size_t)(k + 4) * 9 + tap) * CO + co];
            float2 pv;
            pv.x = __uint_as_float(f2tf32(v0));
            pv.y = __uint_as_float(f2tf32(v1));
            *(float2*)&sm[rowp * SB_ROW + 2 * co] = pv;
        }
        __syncthreads();

        // ---- compute: 9 taps x 4 ksteps ----
#pragma unroll
        for (int tap = 0; tap < 9; ++tap) {
            const int dy = tap / 3 - 1;
            const int dx = tap % 3 - 1;
            const float* pA = &sm[SA_OFF + j * SA_CI
                                  + (warpM + dy + 1) * 66 + 1 + dx + r];
            const float* pB = &sm[(tap * 16 + j) * SB_ROW
                                  + 2 * (warpN * 64 + r)];
#pragma unroll
            for (int s = 0; s < 4; ++s) {
                const float* pAs = pA + s * 8 * SA_CI;
                uint32_t a[4][4];
#pragma unroll
                for (int mt = 0; mt < 4; ++mt) {
                    a[mt][0] = __float_as_uint(pAs[mt * 16]);
                    a[mt][1] = __float_as_uint(pAs[mt * 16 + 8]);
                    a[mt][2] = __float_as_uint(pAs[mt * 16 + 4 * SA_CI]);
                    a[mt][3] = __float_as_uint(pAs[mt * 16 + 8 + 4 * SA_CI]);
                }
                const float* pBs = pB + s * 4 * SB_ROW;
#pragma unroll
                for (int nt = 0; nt < 8; ++nt) {
                    uint2 b = *(const uint2*)&pBs[nt * 16];
#pragma unroll
                    for (int mt = 0; mt < 4; ++mt)
                        mma8(acc[mt][nt], a[mt], b);
                }
            }
        }
    }

    // ---- epilogue: c frag (r, 2j) / (r, 2j+1) / (r+8, ..) ----
    const int y = y0 + warpM;
#pragma unroll
    for (int nt = 0; nt < 8; ++nt) {
        int co = warpN * 64 + nt * 8 + 2 * j;
        float b0 = __ldg(bias + co);
        float b1 = __ldg(bias + co + 1);
        float* o0 = out + (((size_t)n * CO + co) * HW + y) * HW;
#pragma unroll
        for (int mt = 0; mt < 4; ++mt) {
            int x = mt * 16 + r;
            o0[x]               = acc[mt][nt][0] + b0;
            o0[HW * HW + x]     = acc[mt][nt][1] + b1;
            o0[x + 8]           = acc[mt][nt][2] + b0;
            o0[HW * HW + x + 8] = acc[mt][nt][3] + b1;
        }
    }
}

extern "C" void kernel_launch(void* const* d_in, const int* in_sizes, int n_in,
                              void* d_out, int out_size)
{
    const float* in   = (const float*)d_in[0];
    const float* w    = (const float*)d_in[1];
    const float* bias = (const float*)d_in[2];
    float* out        = (float*)d_out;

    cudaFuncSetAttribute(conv_mma_kernel,
                         cudaFuncAttributeMaxDynamicSharedMemorySize, SMEM_BYTES);
    dim3 grid(16, 32);
    conv_mma_kernel<<<grid, 256, SMEM_BYTES>>>(in, w, bias, out);
}

// round 4
// speedup vs baseline: 2.9562x; 1.3001x over previous
#include <cuda_runtime.h>
#include <cstdint>

// Conv2d N=32, Cin=64, 64x64, Cout=128, 3x3 s1 p1, fp32.
// Implicit GEMM on mma.sync.m16n8k8.tf32 (baseline ISA).
// R4: 16 warps (512 thr), warp tile M=64 (x) x N=32 (co), padded A stride
// (424 = 8 mod 32) for conflict-free LDS.
//
// CTA: one n, 4 output rows -> M=256 (4y x 64x), N=128, K=576.
// SMEM: B all 9 taps pre-paired (144 x 264 floats) + A halo (32ci x 424).

#define HW  64
#define CO  128
#define CIN 64

#define SB_ROW    264                 // 8 mod 32 -> conflict-free LDS.64 phases
#define SB_FLOATS (144 * SB_ROW)
#define SA_OFF    SB_FLOATS
#define SA_CI     424                 // 6*66=396 data + pad; 8 mod 32
#define SMEM_BYTES ((SB_FLOATS + 32 * SA_CI) * 4)   // 206,336 B

__device__ __forceinline__ uint32_t f2tf32(float f) {
    uint32_t r; asm("cvt.rna.tf32.f32 %0, %1;" : "=r"(r) : "f"(f)); return r;
}
__device__ __forceinline__ void mma8(float c[4], const uint32_t a[4], uint2 b) {
    asm volatile(
        "mma.sync.aligned.m16n8k8.row.col.f32.tf32.tf32.f32 "
        "{%0,%1,%2,%3}, {%4,%5,%6,%7}, {%8,%9}, {%0,%1,%2,%3};"
        : "+f"(c[0]), "+f"(c[1]), "+f"(c[2]), "+f"(c[3])
        : "r"(a[0]), "r"(a[1]), "r"(a[2]), "r"(a[3]), "r"(b.x), "r"(b.y));
}

__global__ void __launch_bounds__(512, 1)
conv_mma_kernel(const float* __restrict__ in, const float* __restrict__ w,
                const float* __restrict__ bias, float* __restrict__ out)
{
    extern __shared__ float sm[];

    const int tid   = threadIdx.x;
    const int lane  = tid & 31;
    const int warp  = tid >> 5;
    const int warpM = warp >> 2;      // 0..3 -> y row within tile
    const int warpN = warp & 3;       // 0..3 -> co 32-block
    const int y0    = blockIdx.x * 4;
    const int n     = blockIdx.y;

    const int r  = lane >> 2;         // 0..7
    const int j  = lane & 3;          // 0..3

    float acc[4][4][4];
#pragma unroll
    for (int mt = 0; mt < 4; ++mt)
#pragma unroll
        for (int nt = 0; nt < 4; ++nt)
#pragma unroll
            for (int q = 0; q < 4; ++q) acc[mt][nt][q] = 0.f;

    for (int chunk = 0; chunk < 2; ++chunk) {
        const int cib = chunk * 32;
        __syncthreads();   // previous chunk's LDS reads complete

        // ---- stage A: 32 ci x (6 halo rows x 66 cols), tf32-rounded ----
        const float* inb = in + ((size_t)n * CIN + cib) * (HW * HW);
        for (int e = tid; e < 32 * 396; e += 512) {
            int p   = e / 66;         // ci*6 + row
            int col = e - p * 66;
            int ci  = p / 6;
            int row = p - ci * 6;
            int gy  = y0 - 1 + row;
            int gx  = col - 1;
            float v = 0.f;
            if ((unsigned)gy < (unsigned)HW && (unsigned)gx < (unsigned)HW)
                v = inb[((size_t)ci * HW + gy) * HW + gx];
            sm[SA_OFF + ci * SA_CI + row * 66 + col] = __uint_as_float(f2tf32(v));
        }

        // ---- stage B: rows (tap, s, j) hold pairs (k, k+4) per co ----
        const float* wb = w + (size_t)cib * 9 * CO;
        for (int e = tid; e < 144 * 128; e += 512) {
            int co   = e & 127;
            int rowp = e >> 7;            // 0..143
            int tap  = rowp >> 4;
            int s    = (rowp >> 2) & 3;
            int jj   = rowp & 3;
            int k    = s * 8 + jj;
            float v0 = wb[((size_t)k * 9 + tap) * CO + co];
            float v1 = wb[((size_t)(k + 4) * 9 + tap) * CO + co];
            float2 pv;
            pv.x = __uint_as_float(f2tf32(v0));
            pv.y = __uint_as_float(f2tf32(v1));
            *(float2*)&sm[rowp * SB_ROW + 2 * co] = pv;
        }
        __syncthreads();

        // ---- compute: 9 taps x 4 ksteps ----
#pragma unroll
        for (int tap = 0; tap < 9; ++tap) {
            const int dy = tap / 3 - 1;
            const int dx = tap % 3 - 1;
            const float* pA = &sm[SA_OFF + j * SA_CI
                                  + (warpM + dy + 1) * 66 + 1 + dx + r];
            const float* pB = &sm[(tap * 16 + j) * SB_ROW
                                  + 2 * (warpN * 32 + r)];
#pragma unroll
            for (int s = 0; s < 4; ++s) {
                const float* pAs = pA + s * 8 * SA_CI;
                uint32_t a[4][4];
#pragma unroll
                for (int mt = 0; mt < 4; ++mt) {
                    a[mt][0] = __float_as_uint(pAs[mt * 16]);
                    a[mt][1] = __float_as_uint(pAs[mt * 16 + 8]);
                    a[mt][2] = __float_as_uint(pAs[mt * 16 + 4 * SA_CI]);
                    a[mt][3] = __float_as_uint(pAs[mt * 16 + 8 + 4 * SA_CI]);
                }
                const float* pBs = pB + s * 4 * SB_ROW;
#pragma unroll
                for (int nt = 0; nt < 4; ++nt) {
                    uint2 b = *(const uint2*)&pBs[nt * 16];
#pragma unroll
                    for (int mt = 0; mt < 4; ++mt)
                        mma8(acc[mt][nt], a[mt], b);
                }
            }
        }
    }

    // ---- epilogue: c frag rows (r, r+8), cols (2j, 2j+1) ----
    const int y = y0 + warpM;
#pragma unroll
    for (int nt = 0; nt < 4; ++nt) {
        int co = warpN * 32 + nt * 8 + 2 * j;
        float b0 = __ldg(bias + co);
        float b1 = __ldg(bias + co + 1);
        float* o0 = out + (((size_t)n * CO + co) * HW + y) * HW;
#pragma unroll
        for (int mt = 0; mt < 4; ++mt) {
            int x = mt * 16 + r;
            o0[x]               = acc[mt][nt][0] + b0;
            o0[HW * HW + x]     = acc[mt][nt][1] + b1;
            o0[x + 8]           = acc[mt][nt][2] + b0;
            o0[HW * HW + x + 8] = acc[mt][nt][3] + b1;
        }
    }
}

extern "C" void kernel_launch(void* const* d_in, const int* in_sizes, int n_in,
                              void* d_out, int out_size)
{
    const float* in   = (const float*)d_in[0];
    const float* w    = (const float*)d_in[1];
    const float* bias = (const float*)d_in[2];
    float* out        = (float*)d_out;

    cudaFuncSetAttribute(conv_mma_kernel,
                         cudaFuncAttributeMaxDynamicSharedMemorySize, SMEM_BYTES);
    dim3 grid(16, 32);
    conv_mma_kernel<<<grid, 512, SMEM_BYTES>>>(in, w, bias, out);
}